// round 6
// baseline (speedup 1.0000x reference)
#include <cuda_runtime.h>

// Ragged segment mean, fused split-L single kernel (R5: occ + fence tuning):
//   Each (b, split) CTA sums rows {s+split, s+split+NS, ...} of seq[b] into
//   g_partial[b][split][:].  Last-done CTA per b (acq_rel atomic counter)
//   sums the NS partials (L2-hot), divides, writes out[b], resets counter.
//
// seq: [B=2048, L=512, D=512] fp32, begin/end: [B] int32, out: [B, D] fp32.

#define B_DIM 2048
#define L_DIM 512
#define D_DIM 512
#define D_VEC (D_DIM / 4)   // 128 float4 per row
#define NS    4             // splits per batch row

__device__ float g_partial[(size_t)B_DIM * NS * D_DIM];
__device__ int   g_count[B_DIM];   // zero-initialized at load; reset each call

// atomicAdd with acq_rel gpu-scope ordering: release orders prior stores
// (our partial) before the RMW; acquire orders later loads (peer partials)
// after it.  Replaces two __threadfence() calls.
__device__ __forceinline__ int atomic_add_acq_rel(int* addr, int val) {
    int old;
    asm volatile("atom.add.acq_rel.gpu.global.s32 %0, [%1], %2;"
                 : "=r"(old) : "l"(addr), "r"(val) : "memory");
    return old;
}

__global__ __launch_bounds__(D_VEC, 16)
void ragged_mean_fused_kernel(const float* __restrict__ seq,
                              const int* __restrict__ begin,
                              const int* __restrict__ end,
                              float* __restrict__ out) {
    const int b     = blockIdx.x;
    const int split = blockIdx.y;
    const int tid   = threadIdx.x;         // 0..127 -> float4 column

    const int s = __ldg(begin + b);
    const int e = __ldg(end + b);

    const float4* __restrict__ base =
        reinterpret_cast<const float4*>(seq) + (size_t)b * (L_DIM * D_VEC) + tid;

    float4 a = make_float4(0.f, 0.f, 0.f, 0.f);

    int t = s + split;
    // Unrolled x4 over the NS-strided row sequence: 4 independent LDG.128.
    // Pairwise combine keeps the dep chain short with a single accumulator.
    for (; t + 3 * NS < e; t += 4 * NS) {
        float4 v0 = __ldg(base + (size_t)(t + 0 * NS) * D_VEC);
        float4 v1 = __ldg(base + (size_t)(t + 1 * NS) * D_VEC);
        float4 v2 = __ldg(base + (size_t)(t + 2 * NS) * D_VEC);
        float4 v3 = __ldg(base + (size_t)(t + 3 * NS) * D_VEC);
        a.x += (v0.x + v1.x) + (v2.x + v3.x);
        a.y += (v0.y + v1.y) + (v2.y + v3.y);
        a.z += (v0.z + v1.z) + (v2.z + v3.z);
        a.w += (v0.w + v1.w) + (v2.w + v3.w);
    }
    for (; t < e; t += NS) {
        float4 v = __ldg(base + (size_t)t * D_VEC);
        a.x += v.x; a.y += v.y; a.z += v.z; a.w += v.w;
    }

    float4* part = reinterpret_cast<float4*>(g_partial) + (size_t)b * NS * D_VEC;
    part[(size_t)split * D_VEC + tid] = a;

    __shared__ int is_last;
    __syncthreads();                        // all partial STGs issued
    if (tid == 0) {
        int prev = atomic_add_acq_rel(&g_count[b], 1);
        is_last = (prev == NS - 1);
    }
    __syncthreads();

    if (is_last) {
        float4 p0 = part[0 * D_VEC + tid];
        float4 p1 = part[1 * D_VEC + tid];
        float4 p2 = part[2 * D_VEC + tid];
        float4 p3 = part[3 * D_VEC + tid];

        const float inv = 1.0f / (float)(e - s);
        float4 o;
        o.x = ((p0.x + p1.x) + (p2.x + p3.x)) * inv;
        o.y = ((p0.y + p1.y) + (p2.y + p3.y)) * inv;
        o.z = ((p0.z + p1.z) + (p2.z + p3.z)) * inv;
        o.w = ((p0.w + p1.w) + (p2.w + p3.w)) * inv;

        reinterpret_cast<float4*>(out)[(size_t)b * D_VEC + tid] = o;

        if (tid == 0) g_count[b] = 0;   // reset for next graph replay
    }
}

extern "C" void kernel_launch(void* const* d_in, const int* in_sizes, int n_in,
                              void* d_out, int out_size) {
    const float* seq   = (const float*)d_in[0];
    const int*   begin = (const int*)d_in[1];
    const int*   endp  = (const int*)d_in[2];
    float*       out   = (float*)d_out;

    dim3 grid(B_DIM, NS);
    ragged_mean_fused_kernel<<<grid, D_VEC>>>(seq, begin, endp, out);
}

// round 7
// speedup vs baseline: 1.0242x; 1.0242x over previous
#include <cuda_runtime.h>

// Ragged segment mean, fused split-L single kernel (R6: NS=8 + adjacency):
//   Each (split, b) CTA sums rows {s+split, s+split+NS, ...} of seq[b] into
//   g_partial[b][split][:].  Last-done CTA per b (acq_rel atomic counter)
//   sums the NS partials (L2-hot), divides, writes out[b], resets counter.
//   NS=8 tightens the per-CTA work spread (max 32 rows) to shrink the
//   end-of-kernel scheduling tail; grid=(NS,B) keeps the slices of one b
//   adjacent in launch order.
//
// seq: [B=2048, L=512, D=512] fp32, begin/end: [B] int32, out: [B, D] fp32.

#define B_DIM 2048
#define L_DIM 512
#define D_DIM 512
#define D_VEC (D_DIM / 4)   // 128 float4 per row
#define NS    8             // splits per batch row

__device__ float g_partial[(size_t)B_DIM * NS * D_DIM];
__device__ int   g_count[B_DIM];   // zero-initialized at load; reset each call

// atomicAdd with acq_rel gpu-scope ordering: release orders prior stores
// (our partial, via the preceding __syncthreads happens-before chain) before
// the RMW; acquire orders the last CTA's partial loads after it.
__device__ __forceinline__ int atomic_add_acq_rel(int* addr, int val) {
    int old;
    asm volatile("atom.add.acq_rel.gpu.global.s32 %0, [%1], %2;"
                 : "=r"(old) : "l"(addr), "r"(val) : "memory");
    return old;
}

__global__ __launch_bounds__(D_VEC, 16)
void ragged_mean_fused_kernel(const float* __restrict__ seq,
                              const int* __restrict__ begin,
                              const int* __restrict__ end,
                              float* __restrict__ out) {
    const int split = blockIdx.x;          // 0..NS-1 (adjacent slices of b)
    const int b     = blockIdx.y;
    const int tid   = threadIdx.x;         // 0..127 -> float4 column

    const int s = __ldg(begin + b);
    const int e = __ldg(end + b);

    const float4* __restrict__ base =
        reinterpret_cast<const float4*>(seq) + (size_t)b * (L_DIM * D_VEC) + tid;

    float4 a = make_float4(0.f, 0.f, 0.f, 0.f);

    int t = s + split;
    // Unrolled x4 over the NS-strided row sequence: 4 independent LDG.128.
    for (; t + 3 * NS < e; t += 4 * NS) {
        float4 v0 = __ldg(base + (size_t)(t + 0 * NS) * D_VEC);
        float4 v1 = __ldg(base + (size_t)(t + 1 * NS) * D_VEC);
        float4 v2 = __ldg(base + (size_t)(t + 2 * NS) * D_VEC);
        float4 v3 = __ldg(base + (size_t)(t + 3 * NS) * D_VEC);
        a.x += (v0.x + v1.x) + (v2.x + v3.x);
        a.y += (v0.y + v1.y) + (v2.y + v3.y);
        a.z += (v0.z + v1.z) + (v2.z + v3.z);
        a.w += (v0.w + v1.w) + (v2.w + v3.w);
    }
    for (; t < e; t += NS) {
        float4 v = __ldg(base + (size_t)t * D_VEC);
        a.x += v.x; a.y += v.y; a.z += v.z; a.w += v.w;
    }

    float4* part = reinterpret_cast<float4*>(g_partial) + (size_t)b * NS * D_VEC;
    part[(size_t)split * D_VEC + tid] = a;

    __shared__ int is_last;
    __syncthreads();                        // all partial STGs issued
    if (tid == 0) {
        int prev = atomic_add_acq_rel(&g_count[b], 1);
        is_last = (prev == NS - 1);
    }
    __syncthreads();

    if (is_last) {
        float4 p0 = part[0 * D_VEC + tid];
        float4 p1 = part[1 * D_VEC + tid];
        float4 p2 = part[2 * D_VEC + tid];
        float4 p3 = part[3 * D_VEC + tid];
        float4 p4 = part[4 * D_VEC + tid];
        float4 p5 = part[5 * D_VEC + tid];
        float4 p6 = part[6 * D_VEC + tid];
        float4 p7 = part[7 * D_VEC + tid];

        const float inv = 1.0f / (float)(e - s);
        float4 o;
        o.x = (((p0.x + p1.x) + (p2.x + p3.x)) + ((p4.x + p5.x) + (p6.x + p7.x))) * inv;
        o.y = (((p0.y + p1.y) + (p2.y + p3.y)) + ((p4.y + p5.y) + (p6.y + p7.y))) * inv;
        o.z = (((p0.z + p1.z) + (p2.z + p3.z)) + ((p4.z + p5.z) + (p6.z + p7.z))) * inv;
        o.w = (((p0.w + p1.w) + (p2.w + p3.w)) + ((p4.w + p5.w) + (p6.w + p7.w))) * inv;

        reinterpret_cast<float4*>(out)[(size_t)b * D_VEC + tid] = o;

        if (tid == 0) g_count[b] = 0;   // reset for next graph replay
    }
}

extern "C" void kernel_launch(void* const* d_in, const int* in_sizes, int n_in,
                              void* d_out, int out_size) {
    const float* seq   = (const float*)d_in[0];
    const int*   begin = (const int*)d_in[1];
    const int*   endp  = (const int*)d_in[2];
    float*       out   = (float*)d_out;

    dim3 grid(NS, B_DIM);
    ragged_mean_fused_kernel<<<grid, D_VEC>>>(seq, begin, endp, out);
}

// round 8
// speedup vs baseline: 1.0836x; 1.0580x over previous
#include <cuda_runtime.h>

// Ragged segment mean, fused split-L single kernel (R7: L2 traffic diet):
//   - seq read with __ldcs (evict-first streaming: no L2 pollution)
//   - partials written normally (stay L2-resident), read once by the
//     last-done CTA, then discarded via discard.global.L2 so the dirty
//     lines are dropped WITHOUT DRAM writeback.
//
// seq: [B=2048, L=512, D=512] fp32, begin/end: [B] int32, out: [B, D] fp32.

#define B_DIM 2048
#define L_DIM 512
#define D_DIM 512
#define D_VEC (D_DIM / 4)   // 128 float4 per row
#define NS    8             // splits per batch row
#define PART_LINES ((NS * D_DIM * 4) / 128)   // 128B lines per b = 128

__device__ float g_partial[(size_t)B_DIM * NS * D_DIM];
__device__ int   g_count[B_DIM];   // zero-initialized at load; reset each call

__device__ __forceinline__ int atomic_add_acq_rel(int* addr, int val) {
    int old;
    asm volatile("atom.add.acq_rel.gpu.global.s32 %0, [%1], %2;"
                 : "=r"(old) : "l"(addr), "r"(val) : "memory");
    return old;
}

__device__ __forceinline__ void l2_discard_128(const void* p) {
    asm volatile("discard.global.L2 [%0], 128;" :: "l"(p) : "memory");
}

__global__ __launch_bounds__(D_VEC, 16)
void ragged_mean_fused_kernel(const float* __restrict__ seq,
                              const int* __restrict__ begin,
                              const int* __restrict__ end,
                              float* __restrict__ out) {
    const int split = blockIdx.x;          // 0..NS-1
    const int b     = blockIdx.y;
    const int tid   = threadIdx.x;         // 0..127 -> float4 column

    const int s = __ldg(begin + b);
    const int e = __ldg(end + b);

    const float4* __restrict__ base =
        reinterpret_cast<const float4*>(seq) + (size_t)b * (L_DIM * D_VEC) + tid;

    float4 a = make_float4(0.f, 0.f, 0.f, 0.f);

    int t = s + split;
    // Unrolled x4 over the NS-strided row sequence: 4 independent streaming
    // LDG.128 (evict-first) in flight per thread.
    for (; t + 3 * NS < e; t += 4 * NS) {
        float4 v0 = __ldcs(base + (size_t)(t + 0 * NS) * D_VEC);
        float4 v1 = __ldcs(base + (size_t)(t + 1 * NS) * D_VEC);
        float4 v2 = __ldcs(base + (size_t)(t + 2 * NS) * D_VEC);
        float4 v3 = __ldcs(base + (size_t)(t + 3 * NS) * D_VEC);
        a.x += (v0.x + v1.x) + (v2.x + v3.x);
        a.y += (v0.y + v1.y) + (v2.y + v3.y);
        a.z += (v0.z + v1.z) + (v2.z + v3.z);
        a.w += (v0.w + v1.w) + (v2.w + v3.w);
    }
    for (; t < e; t += NS) {
        float4 v = __ldcs(base + (size_t)t * D_VEC);
        a.x += v.x; a.y += v.y; a.z += v.z; a.w += v.w;
    }

    float4* part = reinterpret_cast<float4*>(g_partial) + (size_t)b * NS * D_VEC;
    part[(size_t)split * D_VEC + tid] = a;

    __shared__ int is_last;
    __syncthreads();                        // all partial STGs issued
    if (tid == 0) {
        int prev = atomic_add_acq_rel(&g_count[b], 1);
        is_last = (prev == NS - 1);
    }
    __syncthreads();

    if (is_last) {
        float4 p0 = part[0 * D_VEC + tid];
        float4 p1 = part[1 * D_VEC + tid];
        float4 p2 = part[2 * D_VEC + tid];
        float4 p3 = part[3 * D_VEC + tid];
        float4 p4 = part[4 * D_VEC + tid];
        float4 p5 = part[5 * D_VEC + tid];
        float4 p6 = part[6 * D_VEC + tid];
        float4 p7 = part[7 * D_VEC + tid];

        const float inv = 1.0f / (float)(e - s);
        float4 o;
        o.x = (((p0.x + p1.x) + (p2.x + p3.x)) + ((p4.x + p5.x) + (p6.x + p7.x))) * inv;
        o.y = (((p0.y + p1.y) + (p2.y + p3.y)) + ((p4.y + p5.y) + (p6.y + p7.y))) * inv;
        o.z = (((p0.z + p1.z) + (p2.z + p3.z)) + ((p4.z + p5.z) + (p6.z + p7.z))) * inv;
        o.w = (((p0.w + p1.w) + (p2.w + p3.w)) + ((p4.w + p5.w) + (p6.w + p7.w))) * inv;

        reinterpret_cast<float4*>(out)[(size_t)b * D_VEC + tid] = o;

        // All 128 threads have consumed their partial reads; sync, then drop
        // the dirty partial lines from L2 so they never write back to DRAM.
        __syncthreads();
        const char* pbytes = reinterpret_cast<const char*>(part);
        // PART_LINES == 128 == blockDim.x: one line per thread.
        l2_discard_128(pbytes + (size_t)tid * 128);

        if (tid == 0) g_count[b] = 0;   // reset for next graph replay
    }
}

extern "C" void kernel_launch(void* const* d_in, const int* in_sizes, int n_in,
                              void* d_out, int out_size) {
    const float* seq   = (const float*)d_in[0];
    const int*   begin = (const int*)d_in[1];
    const int*   endp  = (const int*)d_in[2];
    float*       out   = (float*)d_out;

    dim3 grid(NS, B_DIM);
    ragged_mean_fused_kernel<<<grid, D_VEC>>>(seq, begin, endp, out);
}